// round 12
// baseline (speedup 1.0000x reference)
#include <cuda_runtime.h>
#include <cstddef>
#include <cstdint>

#define T_STEPS   4096
#define H_DIM     512
#define N_BATCH   32
#define V_DIM     3

#define GROUPS    8      // independent batch groups
#define BPG       4      // batches per group
#define CPG       16     // CTAs per group
#define COLS      32     // H columns per CTA (16 x 32 = 512)
#define NTHREADS  256
#define NWARPS    8
#define KCHUNK    64     // k per warp

// ---- persistent scratch (no allocation allowed) ----
// double-buffered state: step t reads buf[t&1], writes buf[(t+1)&1]
__device__ __align__(32) float g_state[2][GROUPS][H_DIM][BPG];   // 128KB
// one 128B line PER STEP per group; word c is written ONCE by CTA c
// (pollers of line t-1 never touch the line being written at step t)
__device__ __align__(128) int g_bar[GROUPS][T_STEPS][32];        // 4MB

// Reset per replay: state := 0.01 (both buffers), flag words := 0
__global__ void esn_reset_kernel() {
    const size_t stride = (size_t)gridDim.x * blockDim.x;
    size_t i0 = blockIdx.x * (size_t)blockDim.x + threadIdx.x;
    for (size_t i = i0; i < 32768; i += stride)
        ((float*)g_state)[i] = 0.01f;
    const size_t nbar = (size_t)GROUPS * T_STEPS * 32;
    for (size_t i = i0; i < nbar; i += stride)
        ((int*)g_bar)[i] = 0;
}

__device__ __forceinline__ uint64_t packdup(float v) {
    uint64_t r;
    asm("mov.b64 %0, {%1, %1};" : "=l"(r) : "f"(v));
    return r;
}
#define FMA2(acc, a, b) \
    asm("fma.rn.f32x2 %0, %1, %2, %0;" : "+l"(acc) : "l"(a), "l"(b))

__global__ __launch_bounds__(NTHREADS, 1)
void esn_kernel(const float* __restrict__ X,
                const float* __restrict__ W_in,
                const float* __restrict__ W_int,
                const float* __restrict__ noise,
                float* __restrict__ out)
{
    __shared__ __align__(16) float s_sm[H_DIM][BPG];        // 8KB staged state
    __shared__ __align__(16) float red[NWARPS][BPG][COLS];  // 4KB warp partials

    const int tid   = threadIdx.x;
    const int g     = blockIdx.x >> 4;        // group 0..7
    const int myCta = blockIdx.x & 15;
    const int cbase = myCta * COLS;
    const int w     = tid >> 5;               // warp -> 64-k chunk
    const int lane  = tid & 31;

    // compute-lane decomposition: j2 = col pair (0..15), kh = 32-k half (0/1)
    const int j2 = lane & 15;
    const int kh = lane >> 4;
    const int kbase = w * KCHUNK + kh * 32;

    // ---- one-time: W slice into registers as duplicated f32x2 packs ----
    uint64_t wp[32][2];
    #pragma unroll
    for (int kk = 0; kk < 32; ++kk) {
        #pragma unroll
        for (int j = 0; j < 2; ++j) {
            float wv = __ldg(&W_int[(size_t)(kbase + kk) * H_DIM + cbase + j2 * 2 + j]);
            wp[kk][j] = packdup(wv);
        }
    }

    // reducer-role constants (threads 0..127): one (batch, col) each
    const int rj = tid & 31;             // column-in-slice
    const int rb = (tid >> 5) & 3;       // batch-in-group (valid tid<128)
    const int gb = g * BPG + rb;         // global batch
    const int h  = cbase + rj;           // global column
    float wi0 = 0.f, wi1 = 0.f, wi2 = 0.f;
    if (tid < 128) {
        wi0 = __ldg(&W_in[(size_t)h * V_DIM + 0]);
        wi1 = __ldg(&W_in[(size_t)h * V_DIM + 1]);
        wi2 = __ldg(&W_in[(size_t)h * V_DIM + 2]);
    }

    const int pollw = lane & 15;         // word this lane watches (2x coverage)

    for (int t = 0; t < T_STEPS; ++t) {
        const float* srd = &g_state[t & 1][g][0][0];
        float*       swr = &g_state[(t & 1) ^ 1][g][0][0];

        // ---- prefetch noise & X (independent of state; issued before poll) ----
        float nval = 0.f, x0 = 0.f, x1 = 0.f, x2 = 0.f;
        if (tid < 128) {
            nval = __ldg(noise + ((size_t)t * N_BATCH + gb) * H_DIM + h);
            const float* xp = X + ((size_t)gb * T_STEPS + t) * V_DIM;
            x0 = __ldg(xp + 0); x1 = __ldg(xp + 1); x2 = __ldg(xp + 2);
        }

        // ---- per-warp acquire-poll: 16 write-once words on a dedicated line ----
        if (t > 0) {
            const int* barp = &g_bar[g][t - 1][pollw];
            int v;
            do {
                asm volatile("ld.acquire.gpu.global.b32 %0, [%1];"
                             : "=r"(v) : "l"(barp) : "memory");
            } while (!__all_sync(0xffffffffu, v != 0));
            __syncwarp();   // extend each lane's acquire to the whole warp
        }

        // ---- per-warp state stage (own 64-k slice = 64 float4; .cg) ----
        {
            const float4* src = (const float4*)srd + w * 64 + lane;
            float4*       dst = (float4*)(&s_sm[0][0]) + w * 64 + lane;
            float4 v0 = __ldcg(src);
            float4 v1 = __ldcg(src + 32);
            dst[0]  = v0;
            dst[32] = v1;
            __syncwarp();
        }

        // ---- packed f32x2 compute: 4 acc = 2 cols x 2 batch-pairs ----
        uint64_t acc[2][2];
        acc[0][0] = 0ull; acc[0][1] = 0ull; acc[1][0] = 0ull; acc[1][1] = 0ull;

        const ulonglong2* srow = (const ulonglong2*)&s_sm[kbase][0]; // 1 per k-row
        #pragma unroll
        for (int kk = 0; kk < 32; ++kk) {
            const ulonglong2 p = srow[kk];   // (batch01, batch23) as two f32x2
            FMA2(acc[0][0], p.x, wp[kk][0]);  FMA2(acc[1][0], p.x, wp[kk][1]);
            FMA2(acc[0][1], p.y, wp[kk][0]);  FMA2(acc[1][1], p.y, wp[kk][1]);
        }

        // unpack: a[j][b] = partial for col j2*2+j, batch b
        float a[2][4];
        #pragma unroll
        for (int j = 0; j < 2; ++j) {
            asm("mov.b64 {%0, %1}, %2;" : "=f"(a[j][0]), "=f"(a[j][1]) : "l"(acc[j][0]));
            asm("mov.b64 {%0, %1}, %2;" : "=f"(a[j][2]), "=f"(a[j][3]) : "l"(acc[j][1]));
        }

        // merge the two k-halves (lane ^ 16)
        #pragma unroll
        for (int j = 0; j < 2; ++j)
            #pragma unroll
            for (int b = 0; b < 4; ++b)
                a[j][b] += __shfl_xor_sync(0xffffffffu, a[j][b], 16);

        if (kh == 0) {
            #pragma unroll
            for (int b = 0; b < 4; ++b)
                *(float2*)&red[w][b][j2 * 2] = make_float2(a[0][b], a[1][b]);
        }
        __syncthreads();   // B2: red[] complete (also WAR-gates buf writes)

        // ---- reduce across 8 warps, add input + noise, tanh; publish state ----
        float sv = 0.f;
        if (tid < 128) {
            float sum = 0.f;
            #pragma unroll
            for (int ww = 0; ww < NWARPS; ++ww) sum += red[ww][rb][rj];
            float pre = sum + x0 * wi0 + x1 * wi1 + x2 * wi2 + 0.01f * nval;
            sv = tanhf(pre);
            swr[(size_t)h * BPG + rb] = sv;                      // next-step state
        }
        __syncthreads();   // B3: all state stores before the release store

        // ---- single-writer fire-and-forget release: own word := 1 ----
        if (tid == 0 && t < T_STEPS - 1) {
            asm volatile("st.release.gpu.global.b32 [%0], %1;"
                         :: "l"(&g_bar[g][t][myCta]), "r"(1) : "memory");
        }

        // ---- out store off the critical path (overlaps next step's poll) ----
        if (tid < 128)
            out[((size_t)gb * T_STEPS + t) * H_DIM + h] = sv;
    }
}

extern "C" void kernel_launch(void* const* d_in, const int* in_sizes, int n_in,
                              void* d_out, int out_size)
{
    const float* X     = (const float*)d_in[0];   // (32, 4096, 3)
    const float* W_in  = (const float*)d_in[1];   // (512, 3)
    const float* W_int = (const float*)d_in[2];   // (512, 512)
    const float* noise = (const float*)d_in[3];   // (4096, 32, 512)
    float* out = (float*)d_out;                   // (32, 4096, 512)

    esn_reset_kernel<<<512, 512>>>();
    esn_kernel<<<GROUPS * CPG, NTHREADS>>>(X, W_in, W_int, noise, out);
}

// round 13
// speedup vs baseline: 1.6147x; 1.6147x over previous
#include <cuda_runtime.h>
#include <cstddef>
#include <cstdint>

#define T_STEPS   4096
#define H_DIM     512
#define N_BATCH   32
#define V_DIM     3

#define GROUPS    16     // independent batch groups
#define BPG       2      // batches per group
#define CPG       8      // CTAs per group
#define COLS      64     // H columns per CTA (8 x 64 = 512)
#define NTHREADS  256
#define NWARPS    8
#define KCHUNK    64     // k per warp

// ---- persistent scratch (no allocation allowed) ----
// double-buffered state: step t reads buf[t&1], writes buf[(t+1)&1]
__device__ __align__(32) float g_state[2][GROUPS][H_DIM][BPG];   // 128KB
// one 128B line PER STEP per group (pollers never touch the line being RED-ed)
__device__ __align__(128) int g_bar[GROUPS][T_STEPS][32];        // 8MB

// Reset per replay: state := 0.01 (both buffers), counters := 0
__global__ void esn_reset_kernel() {
    const size_t stride = (size_t)gridDim.x * blockDim.x;
    size_t i0 = blockIdx.x * (size_t)blockDim.x + threadIdx.x;
    for (size_t i = i0; i < 32768; i += stride)       // 2*16*512*2 floats
        ((float*)g_state)[i] = 0.01f;
    const size_t nbar = (size_t)GROUPS * T_STEPS * 32;
    for (size_t i = i0; i < nbar; i += stride)
        ((int*)g_bar)[i] = 0;
}

__device__ __forceinline__ uint64_t packdup(float v) {
    uint64_t r;
    asm("mov.b64 %0, {%1, %1};" : "=l"(r) : "f"(v));
    return r;
}
__device__ __forceinline__ uint64_t pack2(float lo, float hi) {
    uint64_t r;
    asm("mov.b64 %0, {%1, %2};" : "=l"(r) : "f"(lo), "f"(hi));
    return r;
}
#define FMA2(acc, a, b) \
    asm("fma.rn.f32x2 %0, %1, %2, %0;" : "+l"(acc) : "l"(a), "l"(b))

__global__ __launch_bounds__(NTHREADS, 1)
void esn_kernel(const float* __restrict__ X,
                const float* __restrict__ W_in,
                const float* __restrict__ W_int,
                const float* __restrict__ noise,
                float* __restrict__ out)
{
    __shared__ __align__(16) float s_sm[H_DIM][BPG];        // 4KB staged state
    __shared__ __align__(16) float red[NWARPS][BPG][COLS];  // 4KB warp partials

    const int tid   = threadIdx.x;
    const int g     = blockIdx.x >> 3;        // group 0..15
    const int myCta = blockIdx.x & 7;
    const int cbase = myCta * COLS;
    const int w     = tid >> 5;               // warp -> 64-k chunk
    const int lane  = tid & 31;

    // compute-lane decomposition: j4 = col quad (0..15), kh = 32-k half (0/1)
    const int j4 = lane & 15;
    const int kh = lane >> 4;
    const int kbase = w * KCHUNK + kh * 32;
    const int cb = j4 * 4;                    // lane's first col within slice

    // ---- one-time: W slice into registers as column-pair f32x2 packs ----
    // wq[kk][cp] = {W[kbase+kk][cbase+cb+2cp], W[..][cbase+cb+2cp+1]}
    uint64_t wq[32][2];
    #pragma unroll
    for (int kk = 0; kk < 32; ++kk) {
        const float* wr = &W_int[(size_t)(kbase + kk) * H_DIM + cbase + cb];
        wq[kk][0] = pack2(__ldg(wr + 0), __ldg(wr + 1));
        wq[kk][1] = pack2(__ldg(wr + 2), __ldg(wr + 3));
    }

    // reducer-role constants (threads 0..127): one (batch, col) each
    const int rcol = tid & 63;           // column-in-slice
    const int rb   = (tid >> 6) & 1;     // batch-in-group (valid tid<128)
    const int gb   = g * BPG + rb;       // global batch
    const int h    = cbase + rcol;       // global column
    float wi0 = 0.f, wi1 = 0.f, wi2 = 0.f;
    if (tid < 128) {
        wi0 = __ldg(&W_in[(size_t)h * V_DIM + 0]);
        wi1 = __ldg(&W_in[(size_t)h * V_DIM + 1]);
        wi2 = __ldg(&W_in[(size_t)h * V_DIM + 2]);
    }

    for (int t = 0; t < T_STEPS; ++t) {
        const float* srd = &g_state[t & 1][g][0][0];
        float*       swr = &g_state[(t & 1) ^ 1][g][0][0];

        // ---- prefetch noise & X (independent of state; issued before poll) ----
        float nval = 0.f, x0 = 0.f, x1 = 0.f, x2 = 0.f;
        if (tid < 128) {
            nval = __ldg(noise + ((size_t)t * N_BATCH + gb) * H_DIM + h);
            const float* xp = X + ((size_t)gb * T_STEPS + t) * V_DIM;
            x0 = __ldg(xp + 0); x1 = __ldg(xp + 1); x2 = __ldg(xp + 2);
        }

        // ---- per-warp acquire-poll (uniform word, dedicated per-step line) ----
        if (t > 0) {
            const int* barp = &g_bar[g][t - 1][0];
            int v;
            do {
                asm volatile("ld.acquire.gpu.global.b32 %0, [%1];"
                             : "=r"(v) : "l"(barp) : "memory");
            } while (v < CPG);
        }

        // ---- per-warp state stage (own 64-k slice = 32 float4; one ld/lane) ----
        {
            const float4* src = (const float4*)srd + w * 32 + lane;
            float4*       dst = (float4*)(&s_sm[0][0]) + w * 32 + lane;
            *dst = __ldcg(src);
            __syncwarp();
        }

        // ---- packed f32x2 compute: 4 acc = 2 batches x 2 col-pairs ----
        uint64_t acc[2][2];
        acc[0][0] = 0ull; acc[0][1] = 0ull; acc[1][0] = 0ull; acc[1][1] = 0ull;

        const float2* srow = (const float2*)&s_sm[kbase][0]; // 1 per k-row
        #pragma unroll
        for (int kk = 0; kk < 32; ++kk) {
            const float2 s2 = srow[kk];          // state[k][b0], state[k][b1]
            const uint64_t d0 = packdup(s2.x);
            const uint64_t d1 = packdup(s2.y);
            FMA2(acc[0][0], d0, wq[kk][0]);  FMA2(acc[0][1], d0, wq[kk][1]);
            FMA2(acc[1][0], d1, wq[kk][0]);  FMA2(acc[1][1], d1, wq[kk][1]);
        }

        // unpack: a[b][c] = partial for batch b, col cb+c
        float a[2][4];
        #pragma unroll
        for (int b = 0; b < 2; ++b) {
            asm("mov.b64 {%0, %1}, %2;" : "=f"(a[b][0]), "=f"(a[b][1]) : "l"(acc[b][0]));
            asm("mov.b64 {%0, %1}, %2;" : "=f"(a[b][2]), "=f"(a[b][3]) : "l"(acc[b][1]));
        }

        // merge the two k-halves (lane ^ 16)
        #pragma unroll
        for (int b = 0; b < 2; ++b)
            #pragma unroll
            for (int c = 0; c < 4; ++c)
                a[b][c] += __shfl_xor_sync(0xffffffffu, a[b][c], 16);

        if (kh == 0) {
            #pragma unroll
            for (int b = 0; b < 2; ++b)
                *(float4*)&red[w][b][cb] = make_float4(a[b][0], a[b][1], a[b][2], a[b][3]);
        }
        __syncthreads();   // B2: red[] complete (also WAR-gates buf writes)

        // ---- reduce across 8 warps, add input + noise, tanh; publish state ----
        float sv = 0.f;
        if (tid < 128) {
            float sum = 0.f;
            #pragma unroll
            for (int ww = 0; ww < NWARPS; ++ww) sum += red[ww][rb][rcol];
            float pre = sum + x0 * wi0 + x1 * wi1 + x2 * wi2 + 0.01f * nval;
            sv = tanhf(pre);
            swr[(size_t)h * BPG + rb] = sv;                      // next-step state
        }
        __syncthreads();   // B3: all state stores before release; red[] WAR safe

        // ---- fire-and-forget release: single RED on this step's own line ----
        if (tid == 0 && t < T_STEPS - 1) {
            int one = 1;
            asm volatile("red.release.gpu.global.add.s32 [%0], %1;"
                         :: "l"(&g_bar[g][t][0]), "r"(one) : "memory");
        }

        // ---- out store off the critical path (overlaps next step's poll) ----
        if (tid < 128)
            out[((size_t)gb * T_STEPS + t) * H_DIM + h] = sv;
    }
}

extern "C" void kernel_launch(void* const* d_in, const int* in_sizes, int n_in,
                              void* d_out, int out_size)
{
    const float* X     = (const float*)d_in[0];   // (32, 4096, 3)
    const float* W_in  = (const float*)d_in[1];   // (512, 3)
    const float* W_int = (const float*)d_in[2];   // (512, 512)
    const float* noise = (const float*)d_in[3];   // (4096, 32, 512)
    float* out = (float*)d_out;                   // (32, 4096, 512)

    esn_reset_kernel<<<512, 512>>>();
    esn_kernel<<<GROUPS * CPG, NTHREADS>>>(X, W_in, W_int, noise, out);
}